// round 14
// baseline (speedup 1.0000x reference)
#include <cuda_runtime.h>
#include <cuda_fp16.h>
#include <math.h>
#include <stdint.h>

// ---------------------------------------------------------------------------
// GriffinTemporalBlock on GB300 (classic mma.sync fp16 path).
// BK=64 / 3-stage pipelines (tensor pipe was 44% at BK=32 — barrier-starved).
// All GEMMs 1-term fp16.  Dual-GEMMs for (r,i)->a/u and (Wg,Wu)->act.
// B=16, T=1024, D=1024, H=4096.
// ---------------------------------------------------------------------------

constexpr int B = 16;
constexpr int T = 1024;
constexpr int D = 1024;
constexpr int H = 4096;
constexpr int M = B * T;               // 16384
constexpr float EPS = 1.1920929e-07f;
constexpr float C_EXP = 8.0f;

constexpr int SC = 8;                  // scan segments
constexpr int SL = T / SC;             // 128

// ----- scratch (static device globals) -------------------------------------
__device__ __half g_normed_h[(size_t)M * D];
__device__ __half g_conv_h  [(size_t)M * D];
__device__ __half g_prod_h  [(size_t)M * D];   // gelu(b2), then in-place *h
__device__ __half g_n2_h    [(size_t)M * D];
__device__ __half g_act_h   [(size_t)M * H];

__device__ __half g_w1h  [(size_t)D * D];
__device__ __half g_wah  [(size_t)D * D];
__device__ __half g_wxh  [(size_t)D * D];
__device__ __half g_w2h  [(size_t)D * D];
__device__ __half g_wouth[(size_t)D * D];
__device__ __half g_wgh  [(size_t)H * D];
__device__ __half g_wuh  [(size_t)H * D];
__device__ __half g_woh  [(size_t)D * H];

__device__ float  g_b1   [(size_t)M * D];
__device__ __align__(16) float2 g_au [(size_t)M * D];
__device__ float  g_x1   [(size_t)M * D];
__device__ __align__(16) float2 g_seg[(size_t)B * SC * D];
__device__ float  g_hstart[(size_t)B * SC * D];

// ---------------------------------------------------------------------------
// helpers
// ---------------------------------------------------------------------------
__device__ __forceinline__ uint32_t smem_u32(const void* p) {
    uint32_t a;
    asm("{ .reg .u64 t; cvta.to.shared.u64 t, %1; cvt.u32.u64 %0, t; }"
        : "=r"(a) : "l"(p));
    return a;
}

#define CP_ASYNC16(dst, src) \
    asm volatile("cp.async.cg.shared.global [%0], [%1], 16;" :: "r"(dst), "l"(src) : "memory")
#define CP_COMMIT() asm volatile("cp.async.commit_group;" ::: "memory")
#define CP_WAIT1()  asm volatile("cp.async.wait_group 1;" ::: "memory")

#define LDSM4(R, addr) \
    asm volatile("ldmatrix.sync.aligned.m8n8.x4.shared.b16 {%0,%1,%2,%3}, [%4];" \
        : "=r"((R)[0]), "=r"((R)[1]), "=r"((R)[2]), "=r"((R)[3]) : "r"(addr))

#define MMA_F16(d, a, b0v, b1v) \
    asm volatile("mma.sync.aligned.m16n8k16.row.col.f32.f16.f16.f32 " \
        "{%0,%1,%2,%3}, {%4,%5,%6,%7}, {%8,%9}, {%0,%1,%2,%3};" \
        : "+f"((d)[0]), "+f"((d)[1]), "+f"((d)[2]), "+f"((d)[3]) \
        : "r"((a)[0]), "r"((a)[1]), "r"((a)[2]), "r"((a)[3]), "r"(b0v), "r"(b1v))

__device__ __forceinline__ float act_sigmoid(float x) { return 1.0f / (1.0f + expf(-x)); }
__device__ __forceinline__ float act_gelu(float x)    { return 0.5f * x * (1.0f + erff(x * 0.70710678118654752f)); }

// ---------------------------------------------------------------------------
// Single GEMM: 128x128 block, BK=64, 8 warps (64x32 warp tiles), 3-stage
// pipeline, SW128 tiles (128 rows x 128B).
// ---------------------------------------------------------------------------
constexpr int ABYTES = 16384;                  // 128 x 128B
constexpr int STAGE  = 32768;
constexpr int SMEM_B = 3 * STAGE;              // 98304

__device__ __forceinline__ void produce_stage(uint32_t sb,
        const __half* Ab, const __half* Bb,
        int ldA, int ldB, int j, int tid) {
    int k0 = j * 64;
    uint32_t stage = sb + (uint32_t)(j % 3) * STAGE;
    #pragma unroll
    for (int ch = 0; ch < 8; ch++) {
        int c = tid + (ch << 8);                   // 0..2047
        int r = (c & 1023) >> 3;                   // row 0..127
        int q = c & 7;                             // 16B chunk 0..7
        uint32_t off = (uint32_t)(r * 128 + ((q ^ (r & 7)) * 16));   // SW128
        if (c < 1024) {
            CP_ASYNC16(stage + off, Ab + (size_t)r * ldA + k0 + q * 8);
        } else {
            CP_ASYNC16(stage + (uint32_t)ABYTES + off,
                       Bb + (size_t)r * ldB + k0 + q * 8);
        }
    }
    CP_COMMIT();
}

template <int ACT, int RESOP, bool BIAS, int OUTMODE, bool RESHALF>
__global__ void __launch_bounds__(256)
gemm_mma(const __half* __restrict__ A, const __half* __restrict__ Bw,
         int ldA, int ldB, int iters,
         const float* __restrict__ bias, const void* __restrict__ res,
         float* __restrict__ Cf, __half* __restrict__ Cp,
         int N, int ldOut) {
    extern __shared__ char smem[];
    uint32_t sb = smem_u32(smem);
    int tid = threadIdx.x;
    int wid = tid >> 5, lid = tid & 31;
    int wm = wid >> 2, wn = wid & 3;
    int lr = lid & 15, lc = lid >> 4;

    int bm = blockIdx.y, bn = blockIdx.x;
    const __half* Ab = A  + (size_t)(bm * 128) * ldA;
    const __half* Bb = Bw + (size_t)(bn * 128) * ldB;

    float acc[4][4][4];
    #pragma unroll
    for (int i = 0; i < 4; i++)
        #pragma unroll
        for (int j = 0; j < 4; j++)
            #pragma unroll
            for (int q = 0; q < 4; q++) acc[i][j][q] = 0.f;

    // hoisted LDSM row bases
    uint32_t arow[4], brow[2];
    #pragma unroll
    for (int mf = 0; mf < 4; mf++) {
        int row = wm * 64 + mf * 16 + lr;
        arow[mf] = (uint32_t)(row * 128) | ((uint32_t)(row & 7) << 4);
    }
    #pragma unroll
    for (int nf2 = 0; nf2 < 2; nf2++) {
        int row = wn * 32 + nf2 * 16 + lr;
        brow[nf2] = (uint32_t)(row * 128) | ((uint32_t)(row & 7) << 4);
    }
    // arow/brow pack: base = row*128, xor-key preloaded in bits 4-6:
    // addr = stage + (row*128) ^ ((chunk^(row&7))*16) == stage + (arow ^ (chunk*16))
    // because (row*128) has zero bits 4-6 and xor-key sits there.

    produce_stage(sb, Ab, Bb, ldA, ldB, 0, tid);
    produce_stage(sb, Ab, Bb, ldA, ldB, 1, tid);

    for (int it = 0; it < iters; ++it) {
        CP_WAIT1();
        __syncthreads();
        uint32_t sa  = sb + (uint32_t)(it % 3) * STAGE;
        uint32_t sbt = sa + (uint32_t)ABYTES;

        #pragma unroll
        for (int kk = 0; kk < 4; kk++) {
            uint32_t cx = (uint32_t)((kk * 2 + lc) * 16);
            uint32_t a[4][4];
            #pragma unroll
            for (int mf = 0; mf < 4; mf++)
                LDSM4(a[mf], sa + (arow[mf] ^ cx));
            uint32_t bb[2][4];
            #pragma unroll
            for (int nf2 = 0; nf2 < 2; nf2++)
                LDSM4(bb[nf2], sbt + (brow[nf2] ^ cx));
            #pragma unroll
            for (int mf = 0; mf < 4; mf++)
                #pragma unroll
                for (int nf = 0; nf < 4; nf++) {
                    int n2 = nf >> 1, sel = nf & 1;
                    MMA_F16(acc[mf][nf], a[mf], bb[n2][sel], bb[n2][2 + sel]);
                }
        }
        __syncthreads();
        int j = it + 2;
        if (j < iters) produce_stage(sb, Ab, Bb, ldA, ldB, j, tid);
        else           CP_COMMIT();
    }

    int er = lid >> 2;
    int ec = (lid & 3) * 2;
    #pragma unroll
    for (int mf = 0; mf < 4; mf++) {
        #pragma unroll
        for (int nf = 0; nf < 4; nf++) {
            float* cc = acc[mf][nf];
            int row0 = bm * 128 + wm * 64 + mf * 16 + er;
            int col  = bn * 128 + wn * 32 + nf * 8 + ec;
            #pragma unroll
            for (int half = 0; half < 2; half++) {
                int row = row0 + half * 8;
                float v0 = cc[half * 2 + 0];
                float v1 = cc[half * 2 + 1];
                if (BIAS) { v0 += bias[col]; v1 += bias[col + 1]; }
                if (ACT == 1) { v0 = act_sigmoid(v0); v1 = act_sigmoid(v1); }
                if (ACT == 2) { v0 = act_gelu(v0);    v1 = act_gelu(v1); }
                if (RESOP != 0) {
                    float r0, r1;
                    if (RESHALF) {
                        __half2 rv = *reinterpret_cast<const __half2*>(
                            (const __half*)res + (size_t)row * N + col);
                        r0 = __half2float(__low2half(rv));
                        r1 = __half2float(__high2half(rv));
                    } else {
                        float2 rv = *reinterpret_cast<const float2*>(
                            (const float*)res + (size_t)row * N + col);
                        r0 = rv.x; r1 = rv.y;
                    }
                    if (RESOP == 1) { v0 += r0; v1 += r1; }
                    else            { v0 *= r0; v1 *= r1; }
                }
                if (OUTMODE == 2) {
                    *reinterpret_cast<__half2*>(Cp + (size_t)row * ldOut + col) =
                        __halves2half2(__float2half_rn(v0), __float2half_rn(v1));
                } else {
                    *reinterpret_cast<float2*>(Cf + (size_t)row * N + col) = make_float2(v0, v1);
                }
            }
        }
    }
}

// ---------------------------------------------------------------------------
// Dual GEMM: BM=64, BN=128, BK=64, 8 warps, shared A, two B, two accums.
// 3-stage pipeline, stage = A(8KB)+B1(16KB)+B2(16KB) = 40KB, 120KB total.
// EPI 0: a/u epilogue (conv fp16 aux1) -> Cau float2.
// EPI 1: gelu(acc1)*acc2 -> Cp fp16.
// ---------------------------------------------------------------------------
constexpr int D_ABYTES = 8192;                  // 64 x 128B
constexpr int D_BBYTES = 16384;                 // 128 x 128B
constexpr int D_STAGE  = D_ABYTES + 2 * D_BBYTES;   // 40960
constexpr int D_SMEM   = 3 * D_STAGE;               // 122880

__device__ __forceinline__ void produce_stage_dual(uint32_t sb,
        const __half* Ab, const __half* B1b, const __half* B2b,
        int ldA, int ldB, int j, int tid) {
    int k0 = j * 64;
    uint32_t stage = sb + (uint32_t)(j % 3) * D_STAGE;
    #pragma unroll
    for (int ch = 0; ch < 10; ch++) {
        int c = tid + (ch << 8);                   // 0..2559
        if (c < 512) {                             // A: 64 rows x 8 chunks
            int r = c >> 3, q = c & 7;
            uint32_t off = (uint32_t)(r * 128 + ((q ^ (r & 7)) * 16));
            CP_ASYNC16(stage + off, Ab + (size_t)r * ldA + k0 + q * 8);
        } else if (c < 1536) {                     // B1: 128 rows
            int cc = c - 512;
            int r = cc >> 3, q = cc & 7;
            uint32_t off = (uint32_t)(r * 128 + ((q ^ (r & 7)) * 16));
            CP_ASYNC16(stage + (uint32_t)D_ABYTES + off,
                       B1b + (size_t)r * ldB + k0 + q * 8);
        } else {                                   // B2: 128 rows
            int cc = c - 1536;
            int r = cc >> 3, q = cc & 7;
            uint32_t off = (uint32_t)(r * 128 + ((q ^ (r & 7)) * 16));
            CP_ASYNC16(stage + (uint32_t)(D_ABYTES + D_BBYTES) + off,
                       B2b + (size_t)r * ldB + k0 + q * 8);
        }
    }
    CP_COMMIT();
}

template <int EPI>
__global__ void __launch_bounds__(256)
dual_gemm(const __half* __restrict__ A,
          const __half* __restrict__ B1, const __half* __restrict__ B2,
          int ldA, int ldB, int iters,
          const float* __restrict__ bias1, const float* __restrict__ bias2,
          const __half* __restrict__ aux1, const float* __restrict__ aux2,
          float2* __restrict__ Cau, __half* __restrict__ Cp, int N) {
    extern __shared__ char smem[];
    uint32_t sb = smem_u32(smem);
    int tid = threadIdx.x;
    int wid = tid >> 5, lid = tid & 31;
    int wm = wid >> 2, wn = wid & 3;               // 2x4 over 64x128
    int lr = lid & 15, lc = lid >> 4;

    int bm = blockIdx.y, bn = blockIdx.x;
    const __half* Ab  = A  + (size_t)(bm * 64) * ldA;
    const __half* B1b = B1 + (size_t)(bn * 128) * ldB;
    const __half* B2b = B2 + (size_t)(bn * 128) * ldB;

    float acc1[2][4][4], acc2[2][4][4];
    #pragma unroll
    for (int i = 0; i < 2; i++)
        #pragma unroll
        for (int j = 0; j < 4; j++)
            #pragma unroll
            for (int q = 0; q < 4; q++) { acc1[i][j][q] = 0.f; acc2[i][j][q] = 0.f; }

    uint32_t arow[2], brow[2];
    #pragma unroll
    for (int mf = 0; mf < 2; mf++) {
        int row = wm * 32 + mf * 16 + lr;
        arow[mf] = (uint32_t)(row * 128) | ((uint32_t)(row & 7) << 4);
    }
    #pragma unroll
    for (int nf2 = 0; nf2 < 2; nf2++) {
        int row = wn * 32 + nf2 * 16 + lr;
        brow[nf2] = (uint32_t)(row * 128) | ((uint32_t)(row & 7) << 4);
    }

    produce_stage_dual(sb, Ab, B1b, B2b, ldA, ldB, 0, tid);
    produce_stage_dual(sb, Ab, B1b, B2b, ldA, ldB, 1, tid);

    for (int it = 0; it < iters; ++it) {
        CP_WAIT1();
        __syncthreads();
        uint32_t sa  = sb + (uint32_t)(it % 3) * D_STAGE;
        uint32_t sb1 = sa + (uint32_t)D_ABYTES;
        uint32_t sb2 = sb1 + (uint32_t)D_BBYTES;

        #pragma unroll
        for (int kk = 0; kk < 4; kk++) {
            uint32_t cx = (uint32_t)((kk * 2 + lc) * 16);
            uint32_t a[2][4];
            #pragma unroll
            for (int mf = 0; mf < 2; mf++)
                LDSM4(a[mf], sa + (arow[mf] ^ cx));
            uint32_t b1f[2][4], b2f[2][4];
            #pragma unroll
            for (int nf2 = 0; nf2 < 2; nf2++) {
                LDSM4(b1f[nf2], sb1 + (brow[nf2] ^ cx));
                LDSM4(b2f[nf2], sb2 + (brow[nf2] ^ cx));
            }
            #pragma unroll
            for (int mf = 0; mf < 2; mf++)
                #pragma unroll
                for (int nf = 0; nf < 4; nf++) {
                    int n2 = nf >> 1, sel = nf & 1;
                    MMA_F16(acc1[mf][nf], a[mf], b1f[n2][sel], b1f[n2][2 + sel]);
                    MMA_F16(acc2[mf][nf], a[mf], b2f[n2][sel], b2f[n2][2 + sel]);
                }
        }
        __syncthreads();
        int j = it + 2;
        if (j < iters) produce_stage_dual(sb, Ab, B1b, B2b, ldA, ldB, j, tid);
        else           CP_COMMIT();
    }

    int er = lid >> 2;
    int ec = (lid & 3) * 2;
    #pragma unroll
    for (int mf = 0; mf < 2; mf++) {
        #pragma unroll
        for (int nf = 0; nf < 4; nf++) {
            float* c1 = acc1[mf][nf];
            float* c2 = acc2[mf][nf];
            int row0 = bm * 64 + wm * 32 + mf * 16 + er;
            int col  = bn * 128 + wn * 32 + nf * 8 + ec;
            #pragma unroll
            for (int half = 0; half < 2; half++) {
                int row = row0 + half * 8;
                float v0 = c1[half * 2 + 0], v1 = c1[half * 2 + 1];
                float w0 = c2[half * 2 + 0], w1 = c2[half * 2 + 1];
                if (EPI == 0) {
                    float r0 = act_sigmoid(v0 + bias1[col]);
                    float r1 = act_sigmoid(v1 + bias1[col + 1]);
                    float i0 = act_sigmoid(w0 + bias2[col]);
                    float i1 = act_sigmoid(w1 + bias2[col + 1]);
                    size_t idx = (size_t)row * N + col;
                    __half2 cvh = *reinterpret_cast<const __half2*>(aux1 + idx);
                    float cv0 = __half2float(__low2half(cvh));
                    float cv1 = __half2float(__high2half(cvh));
                    float ll0 = aux2[col], ll1 = aux2[col + 1];
                    float ls0 = -log1pf(expf(-ll0));
                    float ls1 = -log1pf(expf(-ll1));
                    float a0 = expf(C_EXP * r0 * ls0);
                    float a1 = expf(C_EXP * r1 * ls1);
                    float gt0 = sqrtf(fmaxf((1.0f - a0) * (1.0f + a0), 1e-6f));
                    float gt1 = sqrtf(fmaxf((1.0f - a1) * (1.0f + a1), 1e-6f));
                    Cau[idx]     = make_float2(a0, gt0 * (i0 * cv0));
                    Cau[idx + 1] = make_float2(a1, gt1 * (i1 * cv1));
                } else {
                    float p0 = act_gelu(v0) * w0;
                    float p1 = act_gelu(v1) * w1;
                    *reinterpret_cast<__half2*>(Cp + (size_t)row * N + col) =
                        __halves2half2(__float2half_rn(p0), __float2half_rn(p1));
                }
            }
        }
    }
}

// ---------------------------------------------------------------------------
// RMSNorm -> fp16
// ---------------------------------------------------------------------------
__global__ void rmsnorm_hi_kernel(const float* __restrict__ x,
                                  const float* __restrict__ w,
                                  __half* __restrict__ outh) {
    int row = blockIdx.x;
    int tid = threadIdx.x;
    const float4* xr = reinterpret_cast<const float4*>(x + (size_t)row * D);
    float4 v = xr[tid];
    float s = v.x * v.x + v.y * v.y + v.z * v.z + v.w * v.w;
    #pragma unroll
    for (int o = 16; o > 0; o >>= 1) s += __shfl_xor_sync(0xffffffffu, s, o);
    __shared__ float sm[8];
    if ((tid & 31) == 0) sm[tid >> 5] = s;
    __syncthreads();
    float tot = 0.f;
    #pragma unroll
    for (int i = 0; i < 8; i++) tot += sm[i];
    float scale = rsqrtf(tot * (1.0f / D) + EPS);
    float4 wv = reinterpret_cast<const float4*>(w)[tid];
    __half2* hp = reinterpret_cast<__half2*>(outh + (size_t)row * D + tid * 4);
    hp[0] = __halves2half2(__float2half_rn(v.x * scale * wv.x),
                           __float2half_rn(v.y * scale * wv.y));
    hp[1] = __halves2half2(__float2half_rn(v.z * scale * wv.z),
                           __float2half_rn(v.w * scale * wv.w));
}

// ---------------------------------------------------------------------------
// Fused weight conversion (8 weights, 1 launch)
// ---------------------------------------------------------------------------
constexpr size_t WCH_S = (size_t)D * D / 4;
constexpr size_t WCH_L = (size_t)H * D / 4;
constexpr size_t WCH_TOTAL = 5 * WCH_S + 3 * WCH_L;

__global__ void whi_all_kernel(const float* __restrict__ W1,
                               const float* __restrict__ Wa,
                               const float* __restrict__ Wx,
                               const float* __restrict__ W2,
                               const float* __restrict__ Wout,
                               const float* __restrict__ Wg,
                               const float* __restrict__ Wu,
                               const float* __restrict__ Wo) {
    size_t c = (size_t)blockIdx.x * blockDim.x + threadIdx.x;
    if (c >= WCH_TOTAL) return;
    const float* src;
    __half* dst;
    size_t off;
    if (c < 5 * WCH_S) {
        int seg = (int)(c / WCH_S);
        off = c % WCH_S;
        src = (seg == 0) ? W1 : (seg == 1) ? Wa : (seg == 2) ? Wx
            : (seg == 3) ? W2 : Wout;
        dst = (seg == 0) ? g_w1h : (seg == 1) ? g_wah : (seg == 2) ? g_wxh
            : (seg == 3) ? g_w2h : g_wouth;
    } else {
        size_t c2 = c - 5 * WCH_S;
        int seg = (int)(c2 / WCH_L);
        off = c2 % WCH_L;
        src = (seg == 0) ? Wg : (seg == 1) ? Wu : Wo;
        dst = (seg == 0) ? g_wgh : (seg == 1) ? g_wuh : g_woh;
    }
    float4 v = reinterpret_cast<const float4*>(src)[off];
    __half2* o = reinterpret_cast<__half2*>(dst + off * 4);
    o[0] = __halves2half2(__float2half_rn(v.x), __float2half_rn(v.y));
    o[1] = __halves2half2(__float2half_rn(v.z), __float2half_rn(v.w));
}

// ---------------------------------------------------------------------------
// Conv (rolling window, fp16-only output, fused conv_buf out)
// ---------------------------------------------------------------------------
__device__ __forceinline__ float4 f4fma(float4 a, float4 b, float4 c) {
    return make_float4(fmaf(a.x, b.x, c.x), fmaf(a.y, b.y, c.y),
                       fmaf(a.z, b.z, c.z), fmaf(a.w, b.w, c.w));
}

__global__ void conv_kernel(const float* __restrict__ conv_buf,
                            const float* __restrict__ conv_w,
                            const float* __restrict__ conv_b,
                            float* __restrict__ out_cb) {
    int b   = blockIdx.y;
    int tc0 = blockIdx.x * 16;
    int d   = threadIdx.x * 4;

    float4 cwr0 = reinterpret_cast<const float4*>(conv_w)[d + 0];
    float4 cwr1 = reinterpret_cast<const float4*>(conv_w)[d + 1];
    float4 cwr2 = reinterpret_cast<const float4*>(conv_w)[d + 2];
    float4 cwr3 = reinterpret_cast<const float4*>(conv_w)[d + 3];
    float4 w0 = make_float4(cwr0.x, cwr1.x, cwr2.x, cwr3.x);
    float4 w1 = make_float4(cwr0.y, cwr1.y, cwr2.y, cwr3.y);
    float4 w2 = make_float4(cwr0.z, cwr1.z, cwr2.z, cwr3.z);
    float4 w3 = make_float4(cwr0.w, cwr1.w, cwr2.w, cwr3.w);
    float4 cb = *reinterpret_cast<const float4*>(conv_b + d);

    const float* b1base = g_b1 + (size_t)b * T * D;
    float4 p3, p2, p1;
    if (tc0 == 0) {
        p3 = *reinterpret_cast<const float4*>(conv_buf + ((size_t)b * 3 + 0) * D + d);
        p2 = *reinterpret_cast<const float4*>(conv_buf + ((size_t)b * 3 + 1) * D + d);
        p1 = *reinterpret_cast<const float4*>(conv_buf + ((size_t)b * 3 + 2) * D + d);
    } else {
        p3 = *reinterpret_cast<const float4*>(b1base + (size_t)(tc0 - 3) * D + d);
        p2 = *reinterpret_cast<const float4*>(b1base + (size_t)(tc0 - 2) * D + d);
        p1 = *reinterpret_cast<const float4*>(b1base + (size_t)(tc0 - 1) * D + d);
    }

    #pragma unroll
    for (int tt = 0; tt < 16; tt++) {
        int t = tc0 + tt;
        float4 cur = *reinterpret_cast<const float4*>(b1base + (size_t)t * D + d);
        float4 o = cb;
        o = f4fma(w0, p3, o);
        o = f4fma(w1, p2, o);
        o = f4fma(w2, p1, o);
        o = f4fma(w3, cur, o);
        size_t gidx = ((size_t)b * T + t) * D + d;
        __half2* hp = reinterpret_cast<__half2*>(g_conv_h + gidx);
        hp[0] = __halves2half2(__float2half_rn(o.x), __float2half_rn(o.y));
        hp[1] = __halves2half2(__float2half_rn(o.z), __float2half_rn(o.w));
        if (t >= T - 3) {
            *reinterpret_cast<float4*>(out_cb + ((size_t)b * 3 + (t - (T - 3))) * D + d) = cur;
        }
        p3 = p2; p2 = p1; p1 = cur;
    }
}

// ---------------------------------------------------------------------------
// Parallel scan (8 segments, 3 passes); emit fuses prod = h * gelu_b2 in-place.
// ---------------------------------------------------------------------------
__global__ void scan_seg_kernel() {
    int g = blockIdx.x * blockDim.x + threadIdx.x;   // B*SC*D
    int d = g % D;
    int c = (g / D) % SC;
    int b = g / (SC * D);
    const float2* au = g_au + ((size_t)b * T + (size_t)c * SL) * D + d;
    float A = 1.0f, U = 0.0f;
    #pragma unroll 8
    for (int t = 0; t < SL; t++) {
        float2 v = au[(size_t)t * D];
        A *= v.x;
        U = fmaf(v.x, U, v.y);
    }
    g_seg[g] = make_float2(A, U);
}

__global__ void scan_combine_kernel(const float* __restrict__ h0,
                                    float* __restrict__ out_h) {
    int g = blockIdx.x * blockDim.x + threadIdx.x;   // B*D
    int d = g % D;
    int b = g / D;
    float h = h0[g];
    #pragma unroll
    for (int c = 0; c < SC; c++) {
        size_t si = ((size_t)b * SC + c) * D + d;
        g_hstart[si] = h;
        float2 s = g_seg[si];
        h = fmaf(s.x, h, s.y);
    }
    out_h[g] = h;
}

__global__ void scan_emit_kernel() {
    int g = blockIdx.x * blockDim.x + threadIdx.x;   // B*SC*D
    int d = g % D;
    int c = (g / D) % SC;
    int b = g / (SC * D);
    size_t base = ((size_t)b * T + (size_t)c * SL) * D + d;
    const float2* au = g_au + base;
    __half* p = g_prod_h + base;
    float h = g_hstart[g];
    #pragma unroll 8
    for (int t = 0; t < SL; t++) {
        float2 v = au[(size_t)t * D];
        h = fmaf(v.x, h, v.y);
        float b2v = __half2float(p[(size_t)t * D]);
        p[(size_t)t * D] = __float2half_rn(h * b2v);
    }
}

// ---------------------------------------------------------------------------
// Launch
// ---------------------------------------------------------------------------
extern "C" void kernel_launch(void* const* d_in, const int* in_sizes, int n_in,
                              void* d_out, int out_size) {
    const float* x_seq      = (const float*)d_in[0];
    const float* h0         = (const float*)d_in[1];
    const float* conv_buf   = (const float*)d_in[2];
    const float* norm1_w    = (const float*)d_in[3];
    const float* W1         = (const float*)d_in[4];
    const float* conv_w     = (const float*)d_in[5];
    const float* conv_b     = (const float*)d_in[6];
    const float* Wa         = (const float*)d_in[7];
    const float* ba         = (const float*)d_in[8];
    const float* Wx         = (const float*)d_in[9];
    const float* bx         = (const float*)d_in[10];
    const float* log_lambda = (const float*)d_in[11];
    const float* W2         = (const float*)d_in[12];
    const float* Wout       = (const float*)d_in[13];
    const float* norm2_w    = (const float*)d_in[14];
    const float* Wg         = (const float*)d_in[15];
    const float* Wu         = (const float*)d_in[16];
    const float* Wo         = (const float*)d_in[17];

    float* out_x2 = (float*)d_out;
    float* out_h  = out_x2 + (size_t)M * D;
    float* out_cb = out_h + (size_t)B * D;

    __half *p_normed, *p_convh, *p_prodh, *p_n2h, *p_acth;
    __half *p_w1, *p_wa, *p_wx, *p_w2, *p_wout, *p_wg, *p_wu, *p_wo;
    float *p_b1, *p_x1;
    float2 *p_au;
    cudaGetSymbolAddress((void**)&p_normed, g_normed_h);
    cudaGetSymbolAddress((void**)&p_convh,  g_conv_h);
    cudaGetSymbolAddress((void**)&p_prodh,  g_prod_h);
    cudaGetSymbolAddress((void**)&p_n2h,    g_n2_h);
    cudaGetSymbolAddress((void**)&p_acth,   g_act_h);
    cudaGetSymbolAddress((void**)&p_w1,     g_w1h);
    cudaGetSymbolAddress((void**)&p_wa,     g_wah);
    cudaGetSymbolAddress((void**)&p_wx,     g_wxh);
    cudaGetSymbolAddress((void**)&p_w2,     g_w2h);
    cudaGetSymbolAddress((void**)&p_wout,   g_wouth);
    cudaGetSymbolAddress((void**)&p_wg,     g_wgh);
    cudaGetSymbolAddress((void**)&p_wu,     g_wuh);
    cudaGetSymbolAddress((void**)&p_wo,     g_woh);
    cudaGetSymbolAddress((void**)&p_b1,     g_b1);
    cudaGetSymbolAddress((void**)&p_au,     g_au);
    cudaGetSymbolAddress((void**)&p_x1,     g_x1);

    auto kPlain  = gemm_mma<0, 0, false, 0, false>;  // b1 -> fp32
    auto kGeluH  = gemm_mma<2, 0, false, 2, false>;  // gelu(b2) -> fp16
    auto kAdd    = gemm_mma<0, 1, false, 0, false>;  // x1, x2
    auto kDualAU = dual_gemm<0>;
    auto kDualGU = dual_gemm<1>;
    cudaFuncSetAttribute(kPlain,  cudaFuncAttributeMaxDynamicSharedMemorySize, SMEM_B);
    cudaFuncSetAttribute(kGeluH,  cudaFuncAttributeMaxDynamicSharedMemorySize, SMEM_B);
    cudaFuncSetAttribute(kAdd,    cudaFuncAttributeMaxDynamicSharedMemorySize, SMEM_B);
    cudaFuncSetAttribute(kDualAU, cudaFuncAttributeMaxDynamicSharedMemorySize, D_SMEM);
    cudaFuncSetAttribute(kDualGU, cudaFuncAttributeMaxDynamicSharedMemorySize, D_SMEM);

    dim3 gD(D / 128, M / 128);       // (8, 128)
    dim3 gDd(D / 128, M / 64);       // (8, 256)
    dim3 gHd(H / 128, M / 64);       // (32, 256)

    // 1. normed = rmsnorm(x_seq) -> fp16
    rmsnorm_hi_kernel<<<M, 256>>>(x_seq, norm1_w, p_normed);
    // 2. weight conversions
    whi_all_kernel<<<(int)((WCH_TOTAL + 255) / 256), 256>>>(W1, Wa, Wx, W2, Wout, Wg, Wu, Wo);
    // 3. b1 = normed @ W1^T -> fp32   (iters = D/64 = 16)
    kPlain<<<gD, 256, SMEM_B>>>(p_normed, p_w1, D, D, 16,
                                nullptr, nullptr, p_b1, nullptr, D, 0);
    // 4. b2h = gelu(normed @ W2^T) -> fp16 (into prod buffer)
    kGeluH<<<gD, 256, SMEM_B>>>(p_normed, p_w2, D, D, 16,
                                nullptr, nullptr, nullptr, p_prodh, D, D);
    // 5. conv (fp16 out, fused out_cb)
    conv_kernel<<<dim3(T / 16, B), 256>>>(conv_buf, conv_w, conv_b, out_cb);
    // 6. dual r/i GEMM + a/u epilogue -> g_au
    kDualAU<<<gDd, 256, D_SMEM>>>(p_convh, p_wa, p_wx, D, D, 16,
                                  ba, bx, p_convh, log_lambda, p_au, nullptr, D);
    // 7-9. parallel scan; emit fuses prod = h * b2h (in-place)
    scan_seg_kernel<<<(B * SC * D) / 256, 256>>>();
    scan_combine_kernel<<<(B * D) / 256, 256>>>(h0, out_h);
    scan_emit_kernel<<<(B * SC * D) / 256, 256>>>();
    // 10. x1 = x_seq + prod @ Wout^T -> fp32
    kAdd<<<gD, 256, SMEM_B>>>(p_prodh, p_wout, D, D, 16,
                              nullptr, x_seq, p_x1, nullptr, D, 0);
    // 11. n2 = rmsnorm(x1) -> fp16
    rmsnorm_hi_kernel<<<M, 256>>>(p_x1, norm2_w, p_n2h);
    // 12. dual Wg/Wu GEMM + gelu-mul epilogue -> act_h
    kDualGU<<<gHd, 256, D_SMEM>>>(p_n2h, p_wg, p_wu, D, D, 16,
                                  nullptr, nullptr, nullptr, nullptr,
                                  nullptr, p_acth, H);
    // 13. x2 = x1 + act @ Wo^T -> out   (iters = H/64 = 64)
    kAdd<<<gD, 256, SMEM_B>>>(p_acth, p_wo, H, H, 64,
                              nullptr, p_x1, out_x2, nullptr, D, 0);
}

// round 16
// speedup vs baseline: 1.6174x; 1.6174x over previous
#include <cuda_runtime.h>
#include <cuda_fp16.h>
#include <math.h>
#include <stdint.h>

// ---------------------------------------------------------------------------
// GriffinTemporalBlock on GB300 (classic mma.sync fp16 path).
// Round 14: single GEMMs use 4 warps x (64x64) tiles (smem-BW balance);
// BK=32 / 4-stage everywhere (round-13 BK=64 regressed via registers).
// B=16, T=1024, D=1024, H=4096.
// ---------------------------------------------------------------------------

constexpr int B = 16;
constexpr int T = 1024;
constexpr int D = 1024;
constexpr int H = 4096;
constexpr int M = B * T;               // 16384
constexpr float EPS = 1.1920929e-07f;
constexpr float C_EXP = 8.0f;

constexpr int SC = 8;                  // scan segments
constexpr int SL = T / SC;             // 128

// ----- scratch (static device globals) -------------------------------------
__device__ __half g_normed_h[(size_t)M * D];
__device__ __half g_conv_h  [(size_t)M * D];
__device__ __half g_prod_h  [(size_t)M * D];   // gelu(b2), then in-place *h
__device__ __half g_n2_h    [(size_t)M * D];
__device__ __half g_act_h   [(size_t)M * H];

__device__ __half g_w1h  [(size_t)D * D];
__device__ __half g_wah  [(size_t)D * D];
__device__ __half g_wxh  [(size_t)D * D];
__device__ __half g_w2h  [(size_t)D * D];
__device__ __half g_wouth[(size_t)D * D];
__device__ __half g_wgh  [(size_t)H * D];
__device__ __half g_wuh  [(size_t)H * D];
__device__ __half g_woh  [(size_t)D * H];

__device__ float  g_b1   [(size_t)M * D];
__device__ __align__(16) float2 g_au [(size_t)M * D];
__device__ float  g_x1   [(size_t)M * D];
__device__ __align__(16) float2 g_seg[(size_t)B * SC * D];
__device__ float  g_hstart[(size_t)B * SC * D];

// ---------------------------------------------------------------------------
// helpers
// ---------------------------------------------------------------------------
__device__ __forceinline__ uint32_t smem_u32(const void* p) {
    uint32_t a;
    asm("{ .reg .u64 t; cvta.to.shared.u64 t, %1; cvt.u32.u64 %0, t; }"
        : "=r"(a) : "l"(p));
    return a;
}

#define CP_ASYNC16(dst, src) \
    asm volatile("cp.async.cg.shared.global [%0], [%1], 16;" :: "r"(dst), "l"(src) : "memory")
#define CP_COMMIT() asm volatile("cp.async.commit_group;" ::: "memory")
#define CP_WAIT2()  asm volatile("cp.async.wait_group 2;" ::: "memory")

#define LDSM4(R, addr) \
    asm volatile("ldmatrix.sync.aligned.m8n8.x4.shared.b16 {%0,%1,%2,%3}, [%4];" \
        : "=r"((R)[0]), "=r"((R)[1]), "=r"((R)[2]), "=r"((R)[3]) : "r"(addr))

#define MMA_F16(d, a, b0v, b1v) \
    asm volatile("mma.sync.aligned.m16n8k16.row.col.f32.f16.f16.f32 " \
        "{%0,%1,%2,%3}, {%4,%5,%6,%7}, {%8,%9}, {%0,%1,%2,%3};" \
        : "+f"((d)[0]), "+f"((d)[1]), "+f"((d)[2]), "+f"((d)[3]) \
        : "r"((a)[0]), "r"((a)[1]), "r"((a)[2]), "r"((a)[3]), "r"(b0v), "r"(b1v))

__device__ __forceinline__ float act_sigmoid(float x) { return 1.0f / (1.0f + expf(-x)); }
__device__ __forceinline__ float act_gelu(float x)    { return 0.5f * x * (1.0f + erff(x * 0.70710678118654752f)); }

// ---------------------------------------------------------------------------
// Single GEMM: 128x128 block, BK=32, 128 threads (4 warps, 64x64 warp tiles),
// 4-stage cp.async pipeline, SW64 tiles (128 rows x 64B).
// smem bytes/FLOP = 0.031 (at smem-BW / tensor balance).
// ---------------------------------------------------------------------------
constexpr int ABYTES = 8192;
constexpr int STAGE  = 16384;
constexpr int SMEM_B = 4 * STAGE;              // 65536

__device__ __forceinline__ void produce_stage(uint32_t sb,
        const __half* Ab, const __half* Bb,
        int ldA, int ldB, int j, int tid) {
    int k0 = j * 32;
    uint32_t stage = sb + (uint32_t)(j & 3) * STAGE;
    #pragma unroll
    for (int ch = 0; ch < 8; ch++) {
        int c = tid + (ch << 7);                   // 0..1023 (128 threads)
        int r = c >> 2, q = c & 3;
        if (c < 512) {
            int qq = q ^ ((r >> 1) & 3);           // SW64
            CP_ASYNC16(stage + (uint32_t)(r * 64 + qq * 16),
                       Ab + (size_t)r * ldA + k0 + q * 8);
        } else {
            int rr = r - 128;
            int qq2 = q ^ ((rr >> 1) & 3);
            CP_ASYNC16(stage + (uint32_t)ABYTES + (uint32_t)(rr * 64 + qq2 * 16),
                       Bb + (size_t)rr * ldB + k0 + q * 8);
        }
    }
    CP_COMMIT();
}

template <int ACT, int RESOP, bool BIAS, int OUTMODE, bool RESHALF>
__global__ void __launch_bounds__(128)
gemm_mma(const __half* __restrict__ A, const __half* __restrict__ Bw,
         int ldA, int ldB, int iters,
         const float* __restrict__ bias, const void* __restrict__ res,
         float* __restrict__ Cf, __half* __restrict__ Cp,
         int N, int ldOut) {
    extern __shared__ char smem[];
    uint32_t sb = smem_u32(smem);
    int tid = threadIdx.x;
    int wid = tid >> 5, lid = tid & 31;
    int wm = wid >> 1, wn = wid & 1;               // warp grid 2x2, tile 64x64
    int lr = lid & 15, lc = lid >> 4;

    int bm = blockIdx.y, bn = blockIdx.x;
    const __half* Ab = A  + (size_t)(bm * 128) * ldA;
    const __half* Bb = Bw + (size_t)(bn * 128) * ldB;

    float acc[4][8][4];
    #pragma unroll
    for (int i = 0; i < 4; i++)
        #pragma unroll
        for (int j = 0; j < 8; j++)
            #pragma unroll
            for (int q = 0; q < 4; q++) acc[i][j][q] = 0.f;

    produce_stage(sb, Ab, Bb, ldA, ldB, 0, tid);
    produce_stage(sb, Ab, Bb, ldA, ldB, 1, tid);
    produce_stage(sb, Ab, Bb, ldA, ldB, 2, tid);

    for (int it = 0; it < iters; ++it) {
        CP_WAIT2();
        __syncthreads();
        uint32_t sa  = sb + (uint32_t)(it & 3) * STAGE;
        uint32_t sbt = sa + (uint32_t)ABYTES;

        #pragma unroll
        for (int kk = 0; kk < 2; kk++) {
            int chunk = kk * 2 + lc;
            uint32_t a[4][4];
            #pragma unroll
            for (int mf = 0; mf < 4; mf++) {
                int row = wm * 64 + mf * 16 + lr;
                int qq = chunk ^ ((row >> 1) & 3);
                LDSM4(a[mf], sa + (uint32_t)(row * 64 + qq * 16));
            }
            uint32_t bb[4][4];
            #pragma unroll
            for (int nf2 = 0; nf2 < 4; nf2++) {
                int row = wn * 64 + nf2 * 16 + lr;
                int qq = chunk ^ ((row >> 1) & 3);
                LDSM4(bb[nf2], sbt + (uint32_t)(row * 64 + qq * 16));
            }
            #pragma unroll
            for (int mf = 0; mf < 4; mf++)
                #pragma unroll
                for (int nf = 0; nf < 8; nf++) {
                    int n2 = nf >> 1, sel = nf & 1;
                    MMA_F16(acc[mf][nf], a[mf], bb[n2][sel], bb[n2][2 + sel]);
                }
        }
        __syncthreads();
        int j = it + 3;
        if (j < iters) produce_stage(sb, Ab, Bb, ldA, ldB, j, tid);
        else           CP_COMMIT();
    }

    int er = lid >> 2;
    int ec = (lid & 3) * 2;
    #pragma unroll
    for (int mf = 0; mf < 4; mf++) {
        #pragma unroll
        for (int nf = 0; nf < 8; nf++) {
            float* cc = acc[mf][nf];
            int row0 = bm * 128 + wm * 64 + mf * 16 + er;
            int col  = bn * 128 + wn * 64 + nf * 8 + ec;
            #pragma unroll
            for (int half = 0; half < 2; half++) {
                int row = row0 + half * 8;
                float v0 = cc[half * 2 + 0];
                float v1 = cc[half * 2 + 1];
                if (BIAS) { v0 += bias[col]; v1 += bias[col + 1]; }
                if (ACT == 1) { v0 = act_sigmoid(v0); v1 = act_sigmoid(v1); }
                if (ACT == 2) { v0 = act_gelu(v0);    v1 = act_gelu(v1); }
                if (RESOP != 0) {
                    float r0, r1;
                    if (RESHALF) {
                        __half2 rv = *reinterpret_cast<const __half2*>(
                            (const __half*)res + (size_t)row * N + col);
                        r0 = __half2float(__low2half(rv));
                        r1 = __half2float(__high2half(rv));
                    } else {
                        float2 rv = *reinterpret_cast<const float2*>(
                            (const float*)res + (size_t)row * N + col);
                        r0 = rv.x; r1 = rv.y;
                    }
                    if (RESOP == 1) { v0 += r0; v1 += r1; }
                    else            { v0 *= r0; v1 *= r1; }
                }
                if (OUTMODE == 2) {
                    *reinterpret_cast<__half2*>(Cp + (size_t)row * ldOut + col) =
                        __halves2half2(__float2half_rn(v0), __float2half_rn(v1));
                } else {
                    *reinterpret_cast<float2*>(Cf + (size_t)row * N + col) = make_float2(v0, v1);
                }
            }
        }
    }
}

// ---------------------------------------------------------------------------
// Dual GEMM (unchanged from round 12): BM=64, BN=128, BK=32, 256 threads,
// shared A, two B, two accums, 4-stage pipeline.
// EPI 0: a/u epilogue -> Cau float2.  EPI 1: gelu(acc1)*acc2 -> Cp fp16.
// ---------------------------------------------------------------------------
constexpr int D_ABYTES = 4096;
constexpr int D_BBYTES = 8192;
constexpr int D_STAGE  = D_ABYTES + 2 * D_BBYTES;   // 20480
constexpr int D_SMEM   = 4 * D_STAGE;               // 81920

__device__ __forceinline__ void produce_stage_dual(uint32_t sb,
        const __half* Ab, const __half* B1b, const __half* B2b,
        int ldA, int ldB, int j, int tid) {
    int k0 = j * 32;
    uint32_t stage = sb + (uint32_t)(j & 3) * D_STAGE;
    #pragma unroll
    for (int ch = 0; ch < 5; ch++) {
        int c = tid + (ch << 8);                   // 0..1279
        if (c < 256) {
            int r = c >> 2, q = c & 3;
            int qq = q ^ ((r >> 1) & 3);
            CP_ASYNC16(stage + (uint32_t)(r * 64 + qq * 16),
                       Ab + (size_t)r * ldA + k0 + q * 8);
        } else if (c < 768) {
            int cc = c - 256;
            int r = cc >> 2, q = cc & 3;
            int qq = q ^ ((r >> 1) & 3);
            CP_ASYNC16(stage + (uint32_t)D_ABYTES + (uint32_t)(r * 64 + qq * 16),
                       B1b + (size_t)r * ldB + k0 + q * 8);
        } else {
            int cc = c - 768;
            int r = cc >> 2, q = cc & 3;
            int qq = q ^ ((r >> 1) & 3);
            CP_ASYNC16(stage + (uint32_t)(D_ABYTES + D_BBYTES)
                             + (uint32_t)(r * 64 + qq * 16),
                       B2b + (size_t)r * ldB + k0 + q * 8);
        }
    }
    CP_COMMIT();
}

template <int EPI>
__global__ void __launch_bounds__(256)
dual_gemm(const __half* __restrict__ A,
          const __half* __restrict__ B1, const __half* __restrict__ B2,
          int ldA, int ldB, int iters,
          const float* __restrict__ bias1, const float* __restrict__ bias2,
          const __half* __restrict__ aux1, const float* __restrict__ aux2,
          float2* __restrict__ Cau, __half* __restrict__ Cp, int N) {
    extern __shared__ char smem[];
    uint32_t sb = smem_u32(smem);
    int tid = threadIdx.x;
    int wid = tid >> 5, lid = tid & 31;
    int wm = wid >> 2, wn = wid & 3;               // 2x4 over 64x128
    int lr = lid & 15, lc = lid >> 4;

    int bm = blockIdx.y, bn = blockIdx.x;
    const __half* Ab  = A  + (size_t)(bm * 64) * ldA;
    const __half* B1b = B1 + (size_t)(bn * 128) * ldB;
    const __half* B2b = B2 + (size_t)(bn * 128) * ldB;

    float acc1[2][4][4], acc2[2][4][4];
    #pragma unroll
    for (int i = 0; i < 2; i++)
        #pragma unroll
        for (int j = 0; j < 4; j++)
            #pragma unroll
            for (int q = 0; q < 4; q++) { acc1[i][j][q] = 0.f; acc2[i][j][q] = 0.f; }

    produce_stage_dual(sb, Ab, B1b, B2b, ldA, ldB, 0, tid);
    produce_stage_dual(sb, Ab, B1b, B2b, ldA, ldB, 1, tid);
    produce_stage_dual(sb, Ab, B1b, B2b, ldA, ldB, 2, tid);

    for (int it = 0; it < iters; ++it) {
        CP_WAIT2();
        __syncthreads();
        uint32_t sa  = sb + (uint32_t)(it & 3) * D_STAGE;
        uint32_t sb1 = sa + (uint32_t)D_ABYTES;
        uint32_t sb2 = sb1 + (uint32_t)D_BBYTES;

        #pragma unroll
        for (int kk = 0; kk < 2; kk++) {
            int chunk = kk * 2 + lc;
            uint32_t a[2][4];
            #pragma unroll
            for (int mf = 0; mf < 2; mf++) {
                int row = wm * 32 + mf * 16 + lr;
                int qq = chunk ^ ((row >> 1) & 3);
                LDSM4(a[mf], sa + (uint32_t)(row * 64 + qq * 16));
            }
            uint32_t b1f[2][4], b2f[2][4];
            #pragma unroll
            for (int nf2 = 0; nf2 < 2; nf2++) {
                int row = wn * 32 + nf2 * 16 + lr;
                int qq = chunk ^ ((row >> 1) & 3);
                LDSM4(b1f[nf2], sb1 + (uint32_t)(row * 64 + qq * 16));
                LDSM4(b2f[nf2], sb2 + (uint32_t)(row * 64 + qq * 16));
            }
            #pragma unroll
            for (int mf = 0; mf < 2; mf++)
                #pragma unroll
                for (int nf = 0; nf < 4; nf++) {
                    int n2 = nf >> 1, sel = nf & 1;
                    MMA_F16(acc1[mf][nf], a[mf], b1f[n2][sel], b1f[n2][2 + sel]);
                    MMA_F16(acc2[mf][nf], a[mf], b2f[n2][sel], b2f[n2][2 + sel]);
                }
        }
        __syncthreads();
        int j = it + 3;
        if (j < iters) produce_stage_dual(sb, Ab, B1b, B2b, ldA, ldB, j, tid);
        else           CP_COMMIT();
    }

    int er = lid >> 2;
    int ec = (lid & 3) * 2;
    #pragma unroll
    for (int mf = 0; mf < 2; mf++) {
        #pragma unroll
        for (int nf = 0; nf < 4; nf++) {
            float* c1 = acc1[mf][nf];
            float* c2 = acc2[mf][nf];
            int row0 = bm * 64 + wm * 32 + mf * 16 + er;
            int col  = bn * 128 + wn * 32 + nf * 8 + ec;
            #pragma unroll
            for (int half = 0; half < 2; half++) {
                int row = row0 + half * 8;
                float v0 = c1[half * 2 + 0], v1 = c1[half * 2 + 1];
                float w0 = c2[half * 2 + 0], w1 = c2[half * 2 + 1];
                if (EPI == 0) {
                    float r0 = act_sigmoid(v0 + bias1[col]);
                    float r1 = act_sigmoid(v1 + bias1[col + 1]);
                    float i0 = act_sigmoid(w0 + bias2[col]);
                    float i1 = act_sigmoid(w1 + bias2[col + 1]);
                    size_t idx = (size_t)row * N + col;
                    __half2 cvh = *reinterpret_cast<const __half2*>(aux1 + idx);
                    float cv0 = __half2float(__low2half(cvh));
                    float cv1 = __half2float(__high2half(cvh));
                    float ll0 = aux2[col], ll1 = aux2[col + 1];
                    float ls0 = -log1pf(expf(-ll0));
                    float ls1 = -log1pf(expf(-ll1));
                    float a0 = expf(C_EXP * r0 * ls0);
                    float a1 = expf(C_EXP * r1 * ls1);
                    float gt0 = sqrtf(fmaxf((1.0f - a0) * (1.0f + a0), 1e-6f));
                    float gt1 = sqrtf(fmaxf((1.0f - a1) * (1.0f + a1), 1e-6f));
                    Cau[idx]     = make_float2(a0, gt0 * (i0 * cv0));
                    Cau[idx + 1] = make_float2(a1, gt1 * (i1 * cv1));
                } else {
                    float p0 = act_gelu(v0) * w0;
                    float p1 = act_gelu(v1) * w1;
                    *reinterpret_cast<__half2*>(Cp + (size_t)row * N + col) =
                        __halves2half2(__float2half_rn(p0), __float2half_rn(p1));
                }
            }
        }
    }
}

// ---------------------------------------------------------------------------
// RMSNorm -> fp16
// ---------------------------------------------------------------------------
__global__ void rmsnorm_hi_kernel(const float* __restrict__ x,
                                  const float* __restrict__ w,
                                  __half* __restrict__ outh) {
    int row = blockIdx.x;
    int tid = threadIdx.x;
    const float4* xr = reinterpret_cast<const float4*>(x + (size_t)row * D);
    float4 v = xr[tid];
    float s = v.x * v.x + v.y * v.y + v.z * v.z + v.w * v.w;
    #pragma unroll
    for (int o = 16; o > 0; o >>= 1) s += __shfl_xor_sync(0xffffffffu, s, o);
    __shared__ float sm[8];
    if ((tid & 31) == 0) sm[tid >> 5] = s;
    __syncthreads();
    float tot = 0.f;
    #pragma unroll
    for (int i = 0; i < 8; i++) tot += sm[i];
    float scale = rsqrtf(tot * (1.0f / D) + EPS);
    float4 wv = reinterpret_cast<const float4*>(w)[tid];
    __half2* hp = reinterpret_cast<__half2*>(outh + (size_t)row * D + tid * 4);
    hp[0] = __halves2half2(__float2half_rn(v.x * scale * wv.x),
                           __float2half_rn(v.y * scale * wv.y));
    hp[1] = __halves2half2(__float2half_rn(v.z * scale * wv.z),
                           __float2half_rn(v.w * scale * wv.w));
}

// ---------------------------------------------------------------------------
// Fused weight conversion (8 weights, 1 launch)
// ---------------------------------------------------------------------------
constexpr size_t WCH_S = (size_t)D * D / 4;
constexpr size_t WCH_L = (size_t)H * D / 4;
constexpr size_t WCH_TOTAL = 5 * WCH_S + 3 * WCH_L;

__global__ void whi_all_kernel(const float* __restrict__ W1,
                               const float* __restrict__ Wa,
                               const float* __restrict__ Wx,
                               const float* __restrict__ W2,
                               const float* __restrict__ Wout,
                               const float* __restrict__ Wg,
                               const float* __restrict__ Wu,
                               const float* __restrict__ Wo) {
    size_t c = (size_t)blockIdx.x * blockDim.x + threadIdx.x;
    if (c >= WCH_TOTAL) return;
    const float* src;
    __half* dst;
    size_t off;
    if (c < 5 * WCH_S) {
        int seg = (int)(c / WCH_S);
        off = c % WCH_S;
        src = (seg == 0) ? W1 : (seg == 1) ? Wa : (seg == 2) ? Wx
            : (seg == 3) ? W2 : Wout;
        dst = (seg == 0) ? g_w1h : (seg == 1) ? g_wah : (seg == 2) ? g_wxh
            : (seg == 3) ? g_w2h : g_wouth;
    } else {
        size_t c2 = c - 5 * WCH_S;
        int seg = (int)(c2 / WCH_L);
        off = c2 % WCH_L;
        src = (seg == 0) ? Wg : (seg == 1) ? Wu : Wo;
        dst = (seg == 0) ? g_wgh : (seg == 1) ? g_wuh : g_woh;
    }
    float4 v = reinterpret_cast<const float4*>(src)[off];
    __half2* o = reinterpret_cast<__half2*>(dst + off * 4);
    o[0] = __halves2half2(__float2half_rn(v.x), __float2half_rn(v.y));
    o[1] = __halves2half2(__float2half_rn(v.z), __float2half_rn(v.w));
}

// ---------------------------------------------------------------------------
// Conv (rolling window, fp16-only output, fused conv_buf out)
// ---------------------------------------------------------------------------
__device__ __forceinline__ float4 f4fma(float4 a, float4 b, float4 c) {
    return make_float4(fmaf(a.x, b.x, c.x), fmaf(a.y, b.y, c.y),
                       fmaf(a.z, b.z, c.z), fmaf(a.w, b.w, c.w));
}

__global__ void conv_kernel(const float* __restrict__ conv_buf,
                            const float* __restrict__ conv_w,
                            const float* __restrict__ conv_b,
                            float* __restrict__ out_cb) {
    int b   = blockIdx.y;
    int tc0 = blockIdx.x * 16;
    int d   = threadIdx.x * 4;

    float4 cwr0 = reinterpret_cast<const float4*>(conv_w)[d + 0];
    float4 cwr1 = reinterpret_cast<const float4*>(conv_w)[d + 1];
    float4 cwr2 = reinterpret_cast<const float4*>(conv_w)[d + 2];
    float4 cwr3 = reinterpret_cast<const float4*>(conv_w)[d + 3];
    float4 w0 = make_float4(cwr0.x, cwr1.x, cwr2.x, cwr3.x);
    float4 w1 = make_float4(cwr0.y, cwr1.y, cwr2.y, cwr3.y);
    float4 w2 = make_float4(cwr0.z, cwr1.z, cwr2.z, cwr3.z);
    float4 w3 = make_float4(cwr0.w, cwr1.w, cwr2.w, cwr3.w);
    float4 cb = *reinterpret_cast<const float4*>(conv_b + d);

    const float* b1base = g_b1 + (size_t)b * T * D;
    float4 p3, p2, p1;
    if (tc0 == 0) {
        p3 = *reinterpret_cast<const float4*>(conv_buf + ((size_t)b * 3 + 0) * D + d);
        p2 = *reinterpret_cast<const float4*>(conv_buf + ((size_t)b * 3 + 1) * D + d);
        p1 = *reinterpret_cast<const float4*>(conv_buf + ((size_t)b * 3 + 2) * D + d);
    } else {
        p3 = *reinterpret_cast<const float4*>(b1base + (size_t)(tc0 - 3) * D + d);
        p2 = *reinterpret_cast<const float4*>(b1base + (size_t)(tc0 - 2) * D + d);
        p1 = *reinterpret_cast<const float4*>(b1base + (size_t)(tc0 - 1) * D + d);
    }

    #pragma unroll
    for (int tt = 0; tt < 16; tt++) {
        int t = tc0 + tt;
        float4 cur = *reinterpret_cast<const float4*>(b1base + (size_t)t * D + d);
        float4 o = cb;
        o = f4fma(w0, p3, o);
        o = f4fma(w1, p2, o);
        o = f4fma(w2, p1, o);
        o = f4fma(w3, cur, o);
        size_t gidx = ((size_t)b * T + t) * D + d;
        __half2* hp = reinterpret_cast<__half2*>(g_conv_h + gidx);
        hp[0] = __halves2half2(__float2half_rn(o.x), __float2half_rn(o.y));
        hp[1] = __halves2half2(__float2half_rn(o.z), __float2half_rn(o.w));
        if (t >= T - 3) {
            *reinterpret_cast<float4*>(out_cb + ((size_t)b * 3 + (t - (T - 3))) * D + d) = cur;
        }
        p3 = p2; p2 = p1; p1 = cur;
    }
}

// ---------------------------------------------------------------------------
// Parallel scan (8 segments, 3 passes); emit fuses prod = h * gelu_b2 in-place.
// ---------------------------------------------------------------------------
__global__ void scan_seg_kernel() {
    int g = blockIdx.x * blockDim.x + threadIdx.x;   // B*SC*D
    int d = g % D;
    int c = (g / D) % SC;
    int b = g / (SC * D);
    const float2* au = g_au + ((size_t)b * T + (size_t)c * SL) * D + d;
    float A = 1.0f, U = 0.0f;
    #pragma unroll 8
    for (int t = 0; t < SL; t++) {
        float2 v = au[(size_t)t * D];
        A *= v.x;
        U = fmaf(v.x, U, v.y);
    }
    g_seg[g] = make_float2(A, U);
}

__global__ void scan_combine_kernel(const float* __restrict__ h0,
                                    float* __restrict__ out_h) {
    int g = blockIdx.x * blockDim.x + threadIdx.x;   // B*D
    int d = g % D;
    int b = g / D;
    float h = h0[g];
    #pragma unroll
    for (int c = 0; c < SC; c++) {
        size_t si = ((size_t)b * SC + c) * D + d;
        g_hstart[si] = h;
        float2 s = g_seg[si];
        h = fmaf(s.x, h, s.y);
    }
    out_h[g] = h;
}

__global__ void scan_emit_kernel() {
    int g = blockIdx.x * blockDim.x + threadIdx.x;   // B*SC*D
    int d = g % D;
    int c = (g / D) % SC;
    int b = g / (SC * D);
    size_t base = ((size_t)b * T + (size_t)c * SL) * D + d;
    const float2* au = g_au + base;
    __half* p = g_prod_h + base;
    float h = g_hstart[g];
    #pragma unroll 8
    for (int t = 0; t < SL; t++) {
        float2 v = au[(size_t)t * D];
        h = fmaf(v.x, h, v.y);
        float b2v = __half2float(p[(size_t)t * D]);
        p[(size_t)t * D] = __float2half_rn(h * b2v);
    }
}

// ---------------------------------------------------------------------------
// Launch
// ---------------------------------------------------------------------------
extern "C" void kernel_launch(void* const* d_in, const int* in_sizes, int n_in,
                              void* d_out, int out_size) {
    const float* x_seq      = (const float*)d_in[0];
    const float* h0         = (const float*)d_in[1];
    const float* conv_buf   = (const float*)d_in[2];
    const float* norm1_w    = (const float*)d_in[3];
    const float* W1         = (const float*)d_in[4];
    const float* conv_w     = (const float*)d_in[5];
    const float* conv_b     = (const float*)d_in[6];
    const float* Wa         = (const float*)d_in[7];
    const float* ba         = (const float*)d_in[8];
    const float* Wx         = (const float*)d_in[9];
    const float* bx         = (const float*)d_in[10];
    const float* log_lambda = (const float*)d_in[11];
    const float* W2         = (const float*)d_in[12];
    const float* Wout       = (const float*)d_in[13];
    const float* norm2_w    = (const float*)d_in[14];
    const float* Wg         = (const float*)d_in[15];
    const float* Wu         = (const float*)d_in[16];
    const float* Wo         = (const float*)d_in[17];

    float* out_x2 = (float*)d_out;
    float* out_h  = out_x2 + (size_t)M * D;
    float* out_cb = out_h + (size_t)B * D;

    __half *p_normed, *p_convh, *p_prodh, *p_n2h, *p_acth;
    __half *p_w1, *p_wa, *p_wx, *p_w2, *p_wout, *p_wg, *p_wu, *p_wo;
    float *p_b1, *p_x1;
    float2 *p_au;
    cudaGetSymbolAddress((void**)&p_normed, g_normed_h);
    cudaGetSymbolAddress((void**)&p_convh,  g_conv_h);
    cudaGetSymbolAddress((void**)&p_prodh,  g_prod_h);
    cudaGetSymbolAddress((void**)&p_n2h,    g_n2_h);
    cudaGetSymbolAddress((void**)&p_acth,   g_act_h);
    cudaGetSymbolAddress((void**)&p_w1,     g_w1h);
    cudaGetSymbolAddress((void**)&p_wa,     g_wah);
    cudaGetSymbolAddress((void**)&p_wx,     g_wxh);
    cudaGetSymbolAddress((void**)&p_w2,     g_w2h);
    cudaGetSymbolAddress((void**)&p_wout,   g_wouth);
    cudaGetSymbolAddress((void**)&p_wg,     g_wgh);
    cudaGetSymbolAddress((void**)&p_wu,     g_wuh);
    cudaGetSymbolAddress((void**)&p_wo,     g_woh);
    cudaGetSymbolAddress((void**)&p_b1,     g_b1);
    cudaGetSymbolAddress((void**)&p_au,     g_au);
    cudaGetSymbolAddress((void**)&p_x1,     g_x1);

    auto kPlain  = gemm_mma<0, 0, false, 0, false>;  // b1 -> fp32
    auto kGeluH  = gemm_mma<2, 0, false, 2, false>;  // gelu(b2) -> fp16
    auto kAdd    = gemm_mma<0, 1, false, 0, false>;  // x1, x2
    auto kDualAU = dual_gemm<0>;
    auto kDualGU = dual_gemm<1>;
    cudaFuncSetAttribute(kPlain,  cudaFuncAttributeMaxDynamicSharedMemorySize, SMEM_B);
    cudaFuncSetAttribute(kGeluH,  cudaFuncAttributeMaxDynamicSharedMemorySize, SMEM_B);
    cudaFuncSetAttribute(kAdd,    cudaFuncAttributeMaxDynamicSharedMemorySize, SMEM_B);
    cudaFuncSetAttribute(kDualAU, cudaFuncAttributeMaxDynamicSharedMemorySize, D_SMEM);
    cudaFuncSetAttribute(kDualGU, cudaFuncAttributeMaxDynamicSharedMemorySize, D_SMEM);

    dim3 gD(D / 128, M / 128);       // (8, 128)
    dim3 gDd(D / 128, M / 64);       // (8, 256)
    dim3 gHd(H / 128, M / 64);       // (32, 256)

    // 1. normed = rmsnorm(x_seq) -> fp16
    rmsnorm_hi_kernel<<<M, 256>>>(x_seq, norm1_w, p_normed);
    // 2. weight conversions
    whi_all_kernel<<<(int)((WCH_TOTAL + 255) / 256), 256>>>(W1, Wa, Wx, W2, Wout, Wg, Wu, Wo);
    // 3. b1 = normed @ W1^T -> fp32
    kPlain<<<gD, 128, SMEM_B>>>(p_normed, p_w1, D, D, 32,
                                nullptr, nullptr, p_b1, nullptr, D, 0);
    // 4. b2h = gelu(normed @ W2^T) -> fp16 (into prod buffer)
    kGeluH<<<gD, 128, SMEM_B>>>(p_normed, p_w2, D, D, 32,
                                nullptr, nullptr, nullptr, p_prodh, D, D);
    // 5. conv (fp16 out, fused out_cb)
    conv_kernel<<<dim3(T / 16, B), 256>>>(conv_buf, conv_w, conv_b, out_cb);
    // 6. dual r/i GEMM + a/u epilogue -> g_au
    kDualAU<<<gDd, 256, D_SMEM>>>(p_convh, p_wa, p_wx, D, D, 32,
                                  ba, bx, p_convh, log_lambda, p_au, nullptr, D);
    // 7-9. parallel scan; emit fuses prod = h * b2h (in-place)
    scan_seg_kernel<<<(B * SC * D) / 256, 256>>>();
    scan_combine_kernel<<<(B * D) / 256, 256>>>(h0, out_h);
    scan_emit_kernel<<<(B * SC * D) / 256, 256>>>();
    // 10. x1 = x_seq + prod @ Wout^T -> fp32
    kAdd<<<gD, 128, SMEM_B>>>(p_prodh, p_wout, D, D, 32,
                              nullptr, x_seq, p_x1, nullptr, D, 0);
    // 11. n2 = rmsnorm(x1) -> fp16
    rmsnorm_hi_kernel<<<M, 256>>>(p_x1, norm2_w, p_n2h);
    // 12. dual Wg/Wu GEMM + gelu-mul epilogue -> act_h
    kDualGU<<<gHd, 256, D_SMEM>>>(p_n2h, p_wg, p_wu, D, D, 32,
                                  nullptr, nullptr, nullptr, nullptr,
                                  nullptr, p_acth, H);
    // 13. x2 = x1 + act @ Wo^T -> out
    kAdd<<<gD, 128, SMEM_B>>>(p_acth, p_wo, H, H, 128,
                              nullptr, p_x1, out_x2, nullptr, D, 0);
}